// round 2
// baseline (speedup 1.0000x reference)
#include <cuda_runtime.h>
#include <cuda_bf16.h>
#include <math.h>
#include <float.h>

// Problem constants (fixed shapes)
#define NB    64
#define CDIM  512
#define TDIM  512
#define NT    (NB * TDIM)          // 32768 tokens
#define KC    1024                 // codes per stage
#define QS    6                    // stages
#define NCT   (NB * CDIM * TDIM)   // 16777216 (quantized_out elements)
#define NTQ   (NT * QS)            // 196608   (all_indices elements)

// Scratch (device globals -- no allocation allowed)
__device__ float g_residual[(size_t)NT * CDIM];   // 64 MB, token-major [NT][C]
__device__ int   g_idx[QS * NT];
__device__ float g_counts[QS * KC];
__device__ float g_cnorm[QS * KC];
__device__ float g_lossA[QS + 2];  // sum ||r||^2 per stage (pre-update residual)
__device__ float g_lossB[QS + 2];  // sum d'_min per stage

__device__ __forceinline__ float warp_sum(float v) {
    v += __shfl_xor_sync(0xffffffffu, v, 16);
    v += __shfl_xor_sync(0xffffffffu, v, 8);
    v += __shfl_xor_sync(0xffffffffu, v, 4);
    v += __shfl_xor_sync(0xffffffffu, v, 2);
    v += __shfl_xor_sync(0xffffffffu, v, 1);
    return v;
}

// ---------------------------------------------------------------------------
// Zero the small stat buffers
// ---------------------------------------------------------------------------
__global__ void zero_stats_kernel() {
    int tid = threadIdx.x;
    for (int i = tid; i < QS * KC; i += blockDim.x) g_counts[i] = 0.0f;
    if (tid < QS + 2) { g_lossA[tid] = 0.0f; g_lossB[tid] = 0.0f; }
}

// ---------------------------------------------------------------------------
// Transpose x (N, C, T) -> residual (N*T, C); also accumulate sum ||x||^2
// into g_lossA[0]. Tiled 32x32 transpose, blockDim (32, 8).
// ---------------------------------------------------------------------------
__global__ void transpose_in_kernel(const float* __restrict__ x) {
    __shared__ float sm[32][33];
    const int n  = blockIdx.z;
    const int c0 = blockIdx.y * 32;
    const int t0 = blockIdx.x * 32;
    const int tx = threadIdx.x, ty = threadIdx.y;

    float ssq = 0.0f;
#pragma unroll
    for (int jj = 0; jj < 4; jj++) {
        int c = c0 + ty + jj * 8;
        float v = x[((size_t)n * CDIM + c) * TDIM + t0 + tx];
        sm[ty + jj * 8][tx] = v;
        ssq += v * v;
    }
    __syncthreads();
#pragma unroll
    for (int jj = 0; jj < 4; jj++) {
        int t = t0 + ty + jj * 8;
        g_residual[((size_t)(n * TDIM + t)) * CDIM + c0 + tx] = sm[tx][ty + jj * 8];
    }
    // block-reduce ssq -> g_lossA[0]
    ssq = warp_sum(ssq);
    __shared__ float red[8];
    if (tx == 0) red[ty] = ssq;
    __syncthreads();
    if (tx == 0 && ty == 0) {
        float s = 0.0f;
#pragma unroll
        for (int w = 0; w < 8; w++) s += red[w];
        atomicAdd(&g_lossA[0], s);
    }
}

// ---------------------------------------------------------------------------
// Codebook squared norms: one warp per (stage, code) row.
// ---------------------------------------------------------------------------
__global__ void cbnorm_kernel(const float* __restrict__ cbs) {
    int row  = blockIdx.x * 8 + (threadIdx.x >> 5);   // 0 .. QS*KC-1
    int lane = threadIdx.x & 31;
    if (row >= QS * KC) return;
    const float* p = cbs + (size_t)row * CDIM;
    float s = 0.0f;
#pragma unroll
    for (int i = lane; i < CDIM; i += 32) { float v = __ldg(p + i); s += v * v; }
    s = warp_sum(s);
    if (lane == 0) g_cnorm[row] = s;
}

// ---------------------------------------------------------------------------
// Fused GEMM + argmin. Per block: 128 tokens x all 1024 codes, inner dim 512.
// 8x8 register micro-tile, 256 threads (16x16).
// d'(token,k) = ||c_k||^2 - 2 * <r, c_k>  (row-constant ||r||^2 dropped).
// Tie-break: smallest code index (matches jnp.argmax first-occurrence).
// ---------------------------------------------------------------------------
#define BM 128
#define BN 128
#define BK 16

__global__ __launch_bounds__(256)
void vq_argmin_kernel(const float* __restrict__ cb, int stage) {
    __shared__ float As[BK][BM];
    __shared__ float Bs[BK][BN];
    __shared__ float sD[BM][16];
    __shared__ int   sJ[BM][16];

    const int tid = threadIdx.x;
    const int tx = tid & 15;        // 0..15 -> column group
    const int ty = tid >> 4;        // 0..15 -> row group
    const int m0 = blockIdx.x * BM;

    float bestD[8];
    int   bestJ[8];
#pragma unroll
    for (int i = 0; i < 8; i++) { bestD[i] = FLT_MAX; bestJ[i] = 0; }

    for (int strip = 0; strip < KC / BN; ++strip) {
        float acc[8][8];
#pragma unroll
        for (int i = 0; i < 8; i++)
#pragma unroll
            for (int j = 0; j < 8; j++) acc[i][j] = 0.0f;

        for (int k0 = 0; k0 < CDIM; k0 += BK) {
            // Load A tile: 128 rows x 16 k (residual)
#pragma unroll
            for (int l = 0; l < 2; l++) {
                int id  = tid + l * 256;          // 0..511
                int row = id >> 2;
                int kq  = (id & 3) * 4;
                float4 v = *(const float4*)&g_residual[((size_t)(m0 + row)) * CDIM + k0 + kq];
                As[kq + 0][row] = v.x; As[kq + 1][row] = v.y;
                As[kq + 2][row] = v.z; As[kq + 3][row] = v.w;
            }
            // Load B tile: 128 codes x 16 k (codebook)
#pragma unroll
            for (int l = 0; l < 2; l++) {
                int id  = tid + l * 256;
                int row = id >> 2;
                int kq  = (id & 3) * 4;
                float4 v = __ldg((const float4*)&cb[((size_t)(strip * BN + row)) * CDIM + k0 + kq]);
                Bs[kq + 0][row] = v.x; Bs[kq + 1][row] = v.y;
                Bs[kq + 2][row] = v.z; Bs[kq + 3][row] = v.w;
            }
            __syncthreads();
#pragma unroll
            for (int kk = 0; kk < BK; kk++) {
                float a[8], b[8];
                *(float4*)&a[0] = *(const float4*)&As[kk][ty * 8];
                *(float4*)&a[4] = *(const float4*)&As[kk][ty * 8 + 4];
                *(float4*)&b[0] = *(const float4*)&Bs[kk][tx * 8];
                *(float4*)&b[4] = *(const float4*)&Bs[kk][tx * 8 + 4];
#pragma unroll
                for (int i = 0; i < 8; i++)
#pragma unroll
                    for (int j = 0; j < 8; j++) acc[i][j] += a[i] * b[j];
            }
            __syncthreads();
        }

        // Argmin update over this column strip
#pragma unroll
        for (int j = 0; j < 8; j++) {
            int col = strip * BN + tx * 8 + j;
            float cn = g_cnorm[stage * KC + col];
#pragma unroll
            for (int i = 0; i < 8; i++) {
                float d = cn - 2.0f * acc[i][j];
                if (d < bestD[i] || (d == bestD[i] && col < bestJ[i])) {
                    bestD[i] = d; bestJ[i] = col;
                }
            }
        }
    }

    // Cross-thread reduction: row (ty*8+i) is shared by the 16 tx threads.
#pragma unroll
    for (int i = 0; i < 8; i++) {
        sD[ty * 8 + i][tx] = bestD[i];
        sJ[ty * 8 + i][tx] = bestJ[i];
    }
    __syncthreads();

    float tokLoss = 0.0f;
    if (tid < BM) {
        float bd = sD[tid][0];
        int   bj = sJ[tid][0];
#pragma unroll
        for (int t2 = 1; t2 < 16; t2++) {
            float d = sD[tid][t2]; int j = sJ[tid][t2];
            if (d < bd || (d == bd && j < bj)) { bd = d; bj = j; }
        }
        int token = m0 + tid;
        g_idx[stage * NT + token] = bj;
        atomicAdd(&g_counts[stage * KC + bj], 1.0f);
        tokLoss = bd;
    }
    if (tid < 128) {  // warps 0..3 fully covered
        float s = warp_sum(tokLoss);
        if ((tid & 31) == 0) atomicAdd(&g_lossB[stage], s);
    }
}

// ---------------------------------------------------------------------------
// Residual update: r -= cb[idx]; optionally accumulate sum ||r_new||^2 into
// g_lossA[stage+1]. float4 over NT*C, 512-thread blocks.
// ---------------------------------------------------------------------------
__global__ __launch_bounds__(512)
void update_kernel(const float* __restrict__ cb, int stage, int accumNext) {
    int i = blockIdx.x * blockDim.x + threadIdx.x;   // over NT*C/4
    int token = i >> 7;        // / (512/4)
    int c4    = i & 127;
    int k = g_idx[stage * NT + token];
    float4 r  = ((float4*)g_residual)[i];
    float4 cv = __ldg((const float4*)cb + (size_t)k * 128 + c4);
    r.x -= cv.x; r.y -= cv.y; r.z -= cv.z; r.w -= cv.w;
    ((float4*)g_residual)[i] = r;
    if (accumNext) {
        float s = r.x * r.x + r.y * r.y + r.z * r.z + r.w * r.w;
        s = warp_sum(s);
        __shared__ float red[16];
        int warp = threadIdx.x >> 5, lane = threadIdx.x & 31;
        if (lane == 0) red[warp] = s;
        __syncthreads();
        if (threadIdx.x == 0) {
            float bs = 0.0f;
#pragma unroll
            for (int w = 0; w < 16; w++) bs += red[w];
            atomicAdd(&g_lossA[stage + 1], bs);
        }
    }
}

// ---------------------------------------------------------------------------
// quantized_out = x - r_final, transposed back to (N, C, T).
// ---------------------------------------------------------------------------
__global__ void output_kernel(const float* __restrict__ x, float* __restrict__ out) {
    __shared__ float sm[32][33];
    const int n  = blockIdx.z;
    const int c0 = blockIdx.y * 32;
    const int t0 = blockIdx.x * 32;
    const int tx = threadIdx.x, ty = threadIdx.y;
#pragma unroll
    for (int jj = 0; jj < 4; jj++) {
        int t = t0 + ty + jj * 8;
        sm[ty + jj * 8][tx] = g_residual[((size_t)(n * TDIM + t)) * CDIM + c0 + tx];
    }
    __syncthreads();
#pragma unroll
    for (int jj = 0; jj < 4; jj++) {
        int c = c0 + ty + jj * 8;
        size_t o = ((size_t)n * CDIM + c) * TDIM + t0 + tx;
        out[o] = x[o] - sm[tx][ty + jj * 8];
    }
}

// ---------------------------------------------------------------------------
// all_indices (N, T, Q) as float, appended after quantized_out.
// ---------------------------------------------------------------------------
__global__ void write_indices_kernel(float* __restrict__ out) {
    int i = blockIdx.x * blockDim.x + threadIdx.x;
    if (i >= NTQ) return;
    int token = i / QS;
    int q     = i - token * QS;
    out[NCT + i] = (float)g_idx[q * NT + token];
}

// ---------------------------------------------------------------------------
// Finalize: mean loss, mean perplexity -> last two output elements.
// ---------------------------------------------------------------------------
__global__ void finalize_kernel(float* __restrict__ out, int writeScalars) {
    __shared__ float red[8];
    __shared__ float acc2[2];
    if (threadIdx.x == 0) { acc2[0] = 0.0f; acc2[1] = 0.0f; }
    __syncthreads();

    for (int s = 0; s < QS; s++) {
        float e = 0.0f;
        for (int k = threadIdx.x; k < KC; k += 256) {
            float p = g_counts[s * KC + k] / ((float)NT + 1e-10f);
            e += p * logf(p + 1e-7f);
        }
        e = warp_sum(e);
        int warp = threadIdx.x >> 5, lane = threadIdx.x & 31;
        if (lane == 0) red[warp] = e;
        __syncthreads();
        if (threadIdx.x == 0) {
            float t = 0.0f;
#pragma unroll
            for (int w = 0; w < 8; w++) t += red[w];
            acc2[1] += expf(-t);                                          // perp
            acc2[0] += (g_lossA[s] + g_lossB[s]) / ((float)NT * (float)CDIM); // loss
        }
        __syncthreads();
    }
    if (threadIdx.x == 0 && writeScalars) {
        out[NCT + NTQ + 0] = acc2[0] / (float)QS;
        out[NCT + NTQ + 1] = acc2[1] / (float)QS;
    }
}

// ---------------------------------------------------------------------------
// Launch
// ---------------------------------------------------------------------------
extern "C" void kernel_launch(void* const* d_in, const int* in_sizes, int n_in,
                              void* d_out, int out_size) {
    const float* x   = (const float*)d_in[0];
    const float* cbs = (const float*)d_in[1];
    // Robust input identification by size (x has NCT elements)
    if (n_in >= 2 && in_sizes[0] != NCT && in_sizes[1] == NCT) {
        const float* tmp = x; x = cbs; cbs = tmp;
    }
    float* out = (float*)d_out;

    zero_stats_kernel<<<1, 256>>>();

    dim3 tb(32, 8);
    dim3 tg(TDIM / 32, CDIM / 32, NB);
    transpose_in_kernel<<<tg, tb>>>(x);

    cbnorm_kernel<<<(QS * KC) / 8, 256>>>(cbs);

    for (int s = 0; s < QS; s++) {
        const float* cb = cbs + (size_t)s * KC * CDIM;
        vq_argmin_kernel<<<NT / BM, 256>>>(cb, s);
        update_kernel<<<(NT * (CDIM / 4)) / 512, 512>>>(cb, s, (s < QS - 1) ? 1 : 0);
    }

    output_kernel<<<tg, tb>>>(x, out);

    if (out_size >= NCT + NTQ)
        write_indices_kernel<<<(NTQ + 255) / 256, 256>>>(out);

    finalize_kernel<<<1, 256>>>(out, (out_size >= NCT + NTQ + 2) ? 1 : 0);
}

// round 5
// speedup vs baseline: 2.3109x; 2.3109x over previous
#include <cuda_runtime.h>
#include <cuda_fp16.h>
#include <math.h>
#include <float.h>
#include <stdint.h>

// ---------------------------------------------------------------------------
// Problem constants (fixed shapes)
// ---------------------------------------------------------------------------
#define NB    64
#define CDIM  512
#define TDIM  512
#define NT    (NB * TDIM)          // 32768 tokens
#define KC    1024                 // codes per stage
#define QS    6                    // stages
#define NCT   (NB * CDIM * TDIM)   // 16777216
#define NTQ   (NT * QS)            // 196608

// GEMM tiling
#define BM 128
#define BN 128
#define BKC 32
#define NSTRIP (KC / BN)           // 8
#define NCHUNK (CDIM / BKC)        // 16
#define NJOB   (NSTRIP * NCHUNK)   // 128

// smem layout (bytes)
#define OFF_CN 0                   // 1024 floats = 4096
#define OFF_SD 4096                // 128*4 floats = 2048
#define OFF_SJ 6144                // 128*4 ints   = 2048
#define OFF_A  8192                // 4 tiles (bufx2, hi/lo)
#define ATILE  10240               // 128 rows * 80 B (32 halfs data + 8 pad)
#define OFF_B  (OFF_A + 4 * ATILE) // 49152
#define SM_VQ  (OFF_B + 4 * ATILE) // 90112

// ---------------------------------------------------------------------------
// Device scratch (no allocation allowed)
// ---------------------------------------------------------------------------
__device__ __align__(16) float  g_r32[(size_t)NT * CDIM];        // fp32 residual master
__device__ __align__(16) __half g_rh[(size_t)NT * CDIM];         // residual hi half
__device__ __align__(16) __half g_rl[(size_t)NT * CDIM];         // residual lo half
__device__ __align__(16) __half g_cbh[(size_t)QS * KC * CDIM];   // codebook hi
__device__ __align__(16) __half g_cbl[(size_t)QS * KC * CDIM];   // codebook lo
__device__ int   g_idx[QS * NT];
__device__ float g_counts[QS * KC];
__device__ float g_cnorm[QS * KC];
__device__ float g_lossA[QS + 2];   // [s+1] = sum ||r_{s+1}||^2 (= stage-s commit-loss numerator)

__device__ __forceinline__ float warp_sum(float v) {
    v += __shfl_xor_sync(0xffffffffu, v, 16);
    v += __shfl_xor_sync(0xffffffffu, v, 8);
    v += __shfl_xor_sync(0xffffffffu, v, 4);
    v += __shfl_xor_sync(0xffffffffu, v, 2);
    v += __shfl_xor_sync(0xffffffffu, v, 1);
    return v;
}

__device__ __forceinline__ void split_h(float v, __half& h, __half& l) {
    h = __float2half_rn(v);
    l = __float2half_rn(v - __half2float(h));
}

__device__ __forceinline__ uint32_t smem_to_u32(const void* p) {
    uint32_t a;
    asm("{ .reg .u64 t; cvta.to.shared.u64 t, %1; cvt.u32.u64 %0, t; }" : "=r"(a) : "l"(p));
    return a;
}
__device__ __forceinline__ uint32_t lds32(uint32_t a) {
    uint32_t v;
    asm volatile("ld.shared.b32 %0, [%1];" : "=r"(v) : "r"(a));
    return v;
}
__device__ __forceinline__ void cp16(uint32_t dst, const void* src) {
    asm volatile("cp.async.cg.shared.global [%0], [%1], 16;" :: "r"(dst), "l"(src) : "memory");
}
__device__ __forceinline__ void cp_commit() { asm volatile("cp.async.commit_group;" ::: "memory"); }
#define CP_WAIT(n) asm volatile("cp.async.wait_group %0;" :: "n"(n) : "memory")

#define MMA16816(d, a0, a1, a2, a3, b0, b1) \
    asm volatile("mma.sync.aligned.m16n8k16.row.col.f32.f16.f16.f32 " \
        "{%0,%1,%2,%3}, {%4,%5,%6,%7}, {%8,%9}, {%0,%1,%2,%3};" \
        : "+f"((d)[0]), "+f"((d)[1]), "+f"((d)[2]), "+f"((d)[3]) \
        : "r"(a0), "r"(a1), "r"(a2), "r"(a3), "r"(b0), "r"(b1))

// ---------------------------------------------------------------------------
// Prep kernels
// ---------------------------------------------------------------------------
__global__ void zero_stats_kernel() {
    int tid = threadIdx.x;
    for (int i = tid; i < QS * KC; i += blockDim.x) g_counts[i] = 0.0f;
    if (tid < QS + 2) g_lossA[tid] = 0.0f;
}

// Split codebooks into half hi/lo
__global__ void split_cb_kernel(const float* __restrict__ cbs) {
    int i = blockIdx.x * blockDim.x + threadIdx.x;   // over QS*KC*CDIM/4
    float4 v = __ldg((const float4*)cbs + i);
    __half h0, h1, h2, h3, l0, l1, l2, l3;
    split_h(v.x, h0, l0); split_h(v.y, h1, l1);
    split_h(v.z, h2, l2); split_h(v.w, h3, l3);
    ((__half2*)g_cbh)[i * 2]     = __halves2half2(h0, h1);
    ((__half2*)g_cbh)[i * 2 + 1] = __halves2half2(h2, h3);
    ((__half2*)g_cbl)[i * 2]     = __halves2half2(l0, l1);
    ((__half2*)g_cbl)[i * 2 + 1] = __halves2half2(l2, l3);
}

__global__ void cbnorm_kernel(const float* __restrict__ cbs) {
    int row  = blockIdx.x * 8 + (threadIdx.x >> 5);
    int lane = threadIdx.x & 31;
    if (row >= QS * KC) return;
    const float* p = cbs + (size_t)row * CDIM;
    float s = 0.0f;
#pragma unroll
    for (int i = lane; i < CDIM; i += 32) { float v = __ldg(p + i); s += v * v; }
    s = warp_sum(s);
    if (lane == 0) g_cnorm[row] = s;
}

// Transpose x (N,C,T) -> r32 (NT,C) + half hi/lo
__global__ void transpose_in_kernel(const float* __restrict__ x) {
    __shared__ float sm[32][33];
    const int n  = blockIdx.z;
    const int c0 = blockIdx.y * 32;
    const int t0 = blockIdx.x * 32;
    const int tx = threadIdx.x, ty = threadIdx.y;
#pragma unroll
    for (int jj = 0; jj < 4; jj++) {
        int c = c0 + ty + jj * 8;
        sm[ty + jj * 8][tx] = x[((size_t)n * CDIM + c) * TDIM + t0 + tx];
    }
    __syncthreads();
#pragma unroll
    for (int jj = 0; jj < 4; jj++) {
        int t = t0 + ty + jj * 8;
        float v = sm[tx][ty + jj * 8];
        size_t o = ((size_t)(n * TDIM + t)) * CDIM + c0 + tx;
        g_r32[o] = v;
        __half h, l; split_h(v, h, l);
        g_rh[o] = h;
        g_rl[o] = l;
    }
}

// ---------------------------------------------------------------------------
// Fused GEMM(argmin) kernel: per CTA 128 tokens x 1024 codes, K=512.
// D = Ah*Bh + Ah*Bl + Al*Bh (fp16 inputs, fp32 accum), legacy mma.sync.
// ---------------------------------------------------------------------------
__global__ __launch_bounds__(256, 2)
void vq_mma_kernel(int stage) {
    extern __shared__ char smem[];
    const uint32_t sb = smem_to_u32(smem);
    const int tid = threadIdx.x;
    const int l   = tid & 31;
    const int w   = tid >> 5;
    const int wm  = w >> 2;          // 0..1  (M half)
    const int wn  = w & 3;           // 0..3  (N quarter)
    const int m0  = blockIdx.x * BM;
    const int cb_stage = stage * KC;

    // stage cnorm (1024 floats) + init running best
    {
        float4 v = __ldg((const float4*)(g_cnorm + cb_stage) + tid);
        ((float4*)(smem + OFF_CN))[tid] = v;
        for (int k = tid; k < 512; k += 256) {
            ((float*)(smem + OFF_SD))[k] = FLT_MAX;
            ((int*)(smem + OFF_SJ))[k]   = 0;
        }
    }
    __syncthreads();

    float acc[64];
#pragma unroll
    for (int i = 0; i < 64; i++) acc[i] = 0.0f;

    const int lr = l >> 2;   // 0..7  row within 8
    const int lc = l & 3;    // 0..3  col group

    // ------------------------------------------------------------------
    auto fill = [&](int job) {
        const int strip = job >> 4;
        const int ch    = job & 15;
        const int buf   = job & 1;
        const int k0    = ch * BKC;
        const int cb0   = cb_stage + strip * BN;
#pragma unroll
        for (int j = 0; j < 8; j++) {
            const int part   = j >> 1;                 // 0:Ah 1:Al 2:Bh 3:Bl
            const int within = tid + (j & 1) * 256;    // 0..511
            const int row    = within >> 2;
            const int kw     = within & 3;
            const __half* src;
            if (part == 0)      src = g_rh  + (size_t)(m0 + row) * CDIM + k0 + kw * 8;
            else if (part == 1) src = g_rl  + (size_t)(m0 + row) * CDIM + k0 + kw * 8;
            else if (part == 2) src = g_cbh + (size_t)(cb0 + row) * CDIM + k0 + kw * 8;
            else                src = g_cbl + (size_t)(cb0 + row) * CDIM + k0 + kw * 8;
            const uint32_t base = (part < 2) ? (sb + OFF_A) : (sb + OFF_B);
            const uint32_t dst  = base + (uint32_t)(buf * 2 + (part & 1)) * ATILE
                                + (uint32_t)row * 80 + (uint32_t)kw * 16;
            cp16(dst, src);
        }
        cp_commit();
    };
    // ------------------------------------------------------------------

    fill(0);

    for (int t = 0; t < NJOB; t++) {
        if (t + 1 < NJOB) { fill(t + 1); CP_WAIT(1); }
        else              { CP_WAIT(0); }
        __syncthreads();

        // compute chunk t
        {
            const int buf = t & 1;
            const uint32_t Ah = sb + OFF_A + (uint32_t)(buf * 2) * ATILE;
            const uint32_t Al = Ah + ATILE;
            const uint32_t Bh = sb + OFF_B + (uint32_t)(buf * 2) * ATILE;
            const uint32_t Bl = Bh + ATILE;
#pragma unroll
            for (int kap = 0; kap < 2; kap++) {
                const uint32_t wofs = (uint32_t)(kap * 8 + lc) * 4;
                uint32_t bh[4][2], bl[4][2];
#pragma unroll
                for (int j = 0; j < 4; j++) {
                    const uint32_t o = (uint32_t)(wn * 32 + j * 8 + lr) * 80 + wofs;
                    bh[j][0] = lds32(Bh + o);  bh[j][1] = lds32(Bh + o + 16);
                    bl[j][0] = lds32(Bl + o);  bl[j][1] = lds32(Bl + o + 16);
                }
#pragma unroll
                for (int i = 0; i < 4; i++) {
                    const uint32_t o = (uint32_t)(wm * 64 + i * 16 + lr) * 80 + wofs;
                    uint32_t ah0 = lds32(Ah + o),        ah1 = lds32(Ah + o + 640);
                    uint32_t ah2 = lds32(Ah + o + 16),   ah3 = lds32(Ah + o + 656);
                    uint32_t al0 = lds32(Al + o),        al1 = lds32(Al + o + 640);
                    uint32_t al2 = lds32(Al + o + 16),   al3 = lds32(Al + o + 656);
#pragma unroll
                    for (int j = 0; j < 4; j++) {
                        float* d = &acc[(i * 4 + j) * 4];
                        MMA16816(d, ah0, ah1, ah2, ah3, bh[j][0], bh[j][1]);
                        MMA16816(d, ah0, ah1, ah2, ah3, bl[j][0], bl[j][1]);
                        MMA16816(d, al0, al1, al2, al3, bh[j][0], bh[j][1]);
                    }
                }
            }
        }

        // strip epilogue: fold distances into smem running best, zero acc
        if ((t & 15) == 15) {
            const int strip = t >> 4;
            const float* cns = (const float*)(smem + OFF_CN);
            float* sd = (float*)(smem + OFF_SD);
            int*   sj = (int*)(smem + OFF_SJ);
#pragma unroll
            for (int i = 0; i < 4; i++) {
#pragma unroll
                for (int dlt = 0; dlt < 2; dlt++) {
                    float bd = FLT_MAX; int bj = 0;
#pragma unroll
                    for (int j = 0; j < 4; j++) {
                        const int col = strip * 128 + wn * 32 + j * 8 + lc * 2;
                        float d0 = cns[col]     - 2.0f * acc[(i * 4 + j) * 4 + dlt * 2];
                        float d1 = cns[col + 1] - 2.0f * acc[(i * 4 + j) * 4 + dlt * 2 + 1];
                        if (d0 < bd) { bd = d0; bj = col; }
                        if (d1 < bd) { bd = d1; bj = col + 1; }
                    }
#pragma unroll
                    for (int off = 1; off < 4; off <<= 1) {
                        float od = __shfl_xor_sync(0xffffffffu, bd, off);
                        int   oj = __shfl_xor_sync(0xffffffffu, bj, off);
                        if (od < bd || (od == bd && oj < bj)) { bd = od; bj = oj; }
                    }
                    if (lc == 0) {
                        const int row = wm * 64 + i * 16 + lr + dlt * 8;
                        const int s4  = row * 4 + wn;
                        if (bd < sd[s4] || (bd == sd[s4] && bj < sj[s4])) {
                            sd[s4] = bd; sj[s4] = bj;
                        }
                    }
                }
            }
#pragma unroll
            for (int i = 0; i < 64; i++) acc[i] = 0.0f;
        }
        __syncthreads();
    }

    // final cross-warp reduce + write indices/counts
    if (tid < 128) {
        const float* sd = (const float*)(smem + OFF_SD);
        const int*   sj = (const int*)(smem + OFF_SJ);
        float bd = sd[tid * 4];
        int   bj = sj[tid * 4];
#pragma unroll
        for (int q = 1; q < 4; q++) {
            float d = sd[tid * 4 + q]; int j = sj[tid * 4 + q];
            if (d < bd || (d == bd && j < bj)) { bd = d; bj = j; }
        }
        g_idx[stage * NT + m0 + tid] = bj;
        atomicAdd(&g_counts[cb_stage + bj], 1.0f);
    }
}

// ---------------------------------------------------------------------------
// Residual update: fp32 master chain r -= cb[idx]; derive halves; accumulate
// ||r_new||^2 (commit-loss numerator for this stage).
// ---------------------------------------------------------------------------
__global__ __launch_bounds__(512)
void update_kernel(const float* __restrict__ cb, int stage) {
    int i = blockIdx.x * blockDim.x + threadIdx.x;   // over NT*CDIM/4
    int token = i >> 7;
    int c4    = i & 127;
    int k = g_idx[stage * NT + token];
    float4 r  = ((const float4*)g_r32)[i];
    float4 cv = __ldg((const float4*)cb + (size_t)k * 128 + c4);
    r.x -= cv.x; r.y -= cv.y; r.z -= cv.z; r.w -= cv.w;
    ((float4*)g_r32)[i] = r;

    __half h0, h1, h2, h3, l0, l1, l2, l3;
    split_h(r.x, h0, l0); split_h(r.y, h1, l1);
    split_h(r.z, h2, l2); split_h(r.w, h3, l3);
    ((__half2*)g_rh)[i * 2]     = __halves2half2(h0, h1);
    ((__half2*)g_rh)[i * 2 + 1] = __halves2half2(h2, h3);
    ((__half2*)g_rl)[i * 2]     = __halves2half2(l0, l1);
    ((__half2*)g_rl)[i * 2 + 1] = __halves2half2(l2, l3);

    float s = r.x * r.x + r.y * r.y + r.z * r.z + r.w * r.w;
    s = warp_sum(s);
    __shared__ float red[16];
    int warp = threadIdx.x >> 5, lane = threadIdx.x & 31;
    if (lane == 0) red[warp] = s;
    __syncthreads();
    if (threadIdx.x == 0) {
        float bs = 0.0f;
#pragma unroll
        for (int wq = 0; wq < 16; wq++) bs += red[wq];
        atomicAdd(&g_lossA[stage + 1], bs);
    }
}

// ---------------------------------------------------------------------------
// quantized_out = x - r_final, transposed back to (N, C, T)
// ---------------------------------------------------------------------------
__global__ void output_kernel(const float* __restrict__ x, float* __restrict__ out) {
    __shared__ float sm[32][33];
    const int n  = blockIdx.z;
    const int c0 = blockIdx.y * 32;
    const int t0 = blockIdx.x * 32;
    const int tx = threadIdx.x, ty = threadIdx.y;
#pragma unroll
    for (int jj = 0; jj < 4; jj++) {
        int t = t0 + ty + jj * 8;
        sm[ty + jj * 8][tx] = g_r32[((size_t)(n * TDIM + t)) * CDIM + c0 + tx];
    }
    __syncthreads();
#pragma unroll
    for (int jj = 0; jj < 4; jj++) {
        int c = c0 + ty + jj * 8;
        size_t o = ((size_t)n * CDIM + c) * TDIM + t0 + tx;
        out[o] = x[o] - sm[tx][ty + jj * 8];
    }
}

__global__ void write_indices_kernel(float* __restrict__ out) {
    int i = blockIdx.x * blockDim.x + threadIdx.x;
    if (i >= NTQ) return;
    int token = i / QS;
    int q     = i - token * QS;
    out[NCT + i] = (float)g_idx[q * NT + token];
}

__global__ void finalize_kernel(float* __restrict__ out, int writeScalars) {
    __shared__ float red[8];
    __shared__ float acc2[2];
    if (threadIdx.x == 0) { acc2[0] = 0.0f; acc2[1] = 0.0f; }
    __syncthreads();
    for (int s = 0; s < QS; s++) {
        float e = 0.0f;
        for (int k = threadIdx.x; k < KC; k += 256) {
            float p = g_counts[s * KC + k] / ((float)NT + 1e-10f);
            e += p * logf(p + 1e-7f);
        }
        e = warp_sum(e);
        int warp = threadIdx.x >> 5, lane = threadIdx.x & 31;
        if (lane == 0) red[warp] = e;
        __syncthreads();
        if (threadIdx.x == 0) {
            float t = 0.0f;
#pragma unroll
            for (int wq = 0; wq < 8; wq++) t += red[wq];
            acc2[1] += expf(-t);
            acc2[0] += g_lossA[s + 1] / ((float)NT * (float)CDIM);
        }
        __syncthreads();
    }
    if (threadIdx.x == 0 && writeScalars) {
        out[NCT + NTQ + 0] = acc2[0] / (float)QS;
        out[NCT + NTQ + 1] = acc2[1] / (float)QS;
    }
}

// ---------------------------------------------------------------------------
// Launch
// ---------------------------------------------------------------------------
extern "C" void kernel_launch(void* const* d_in, const int* in_sizes, int n_in,
                              void* d_out, int out_size) {
    const float* x   = (const float*)d_in[0];
    const float* cbs = (const float*)d_in[1];
    if (n_in >= 2 && in_sizes[0] != NCT && in_sizes[1] == NCT) {
        const float* tmp = x; x = cbs; cbs = tmp;
    }
    float* out = (float*)d_out;

    cudaFuncSetAttribute(vq_mma_kernel, cudaFuncAttributeMaxDynamicSharedMemorySize, SM_VQ);

    zero_stats_kernel<<<1, 256>>>();
    split_cb_kernel<<<(QS * KC * CDIM / 4) / 256, 256>>>(cbs);
    cbnorm_kernel<<<(QS * KC) / 8, 256>>>(cbs);

    dim3 tb(32, 8);
    dim3 tg(TDIM / 32, CDIM / 32, NB);
    transpose_in_kernel<<<tg, tb>>>(x);

    for (int s = 0; s < QS; s++) {
        const float* cb = cbs + (size_t)s * KC * CDIM;
        vq_mma_kernel<<<NT / BM, 256, SM_VQ>>>(s);
        update_kernel<<<(NT * (CDIM / 4)) / 512, 512>>>(cb, s);
    }

    output_kernel<<<tg, tb>>>(x, out);

    if (out_size >= NCT + NTQ)
        write_indices_kernel<<<(NTQ + 255) / 256, 256>>>(out);

    finalize_kernel<<<1, 256>>>(out, (out_size >= NCT + NTQ + 2) ? 1 : 0);
}